// round 1
// baseline (speedup 1.0000x reference)
#include <cuda_runtime.h>

#define NN 16384
#define DD 64

static __device__ __constant__ const float kDummy = 0.f; // (no-op, keeps nvcc quiet on some configs)

constexpr float TAU_F   = 0.28f;
constexpr float EPS_F   = 1e-8f;
constexpr float LOG2E_F = 1.4426950408889634f;

// Scratch (allocation-free: __device__ globals)
__device__ float g_u[NN * DD];                 // normalized u, pre-scaled by log2e/TAU
__device__ float g_w[NN * DD];                 // normalized i + normalized u
__device__ float g_pos[NN];                    // pos logit = (u_n . i_n)/TAU
__device__ float g_partial[(NN / 128) * NN];   // per-column-block partial row sums (8 MB)
__device__ float g_blocksum[64];

// ---------------------------------------------------------------------------
// Kernel 1: row L2-normalize both inputs; build w = i_n + u_n; pos logits.
// One warp per row (D=64 -> 2 floats/lane).
// ---------------------------------------------------------------------------
__global__ void prep_kernel(const float* __restrict__ U, const float* __restrict__ I) {
    int row  = blockIdx.x * 8 + (threadIdx.x >> 5);
    int lane = threadIdx.x & 31;

    const float* up = U + (size_t)row * DD;
    const float* ip = I + (size_t)row * DD;
    float u0 = up[lane], u1 = up[lane + 32];
    float i0 = ip[lane], i1 = ip[lane + 32];

    float su = u0 * u0 + u1 * u1;
    float si = i0 * i0 + i1 * i1;
#pragma unroll
    for (int o = 16; o; o >>= 1) {
        su += __shfl_xor_sync(0xffffffffu, su, o);
        si += __shfl_xor_sync(0xffffffffu, si, o);
    }
    float inu = rsqrtf(fmaxf(su, 1e-24f));
    float ini = rsqrtf(fmaxf(si, 1e-24f));

    float un0 = u0 * inu, un1 = u1 * inu;
    float vn0 = i0 * ini, vn1 = i1 * ini;

    float d = un0 * vn0 + un1 * vn1;
#pragma unroll
    for (int o = 16; o; o >>= 1) d += __shfl_xor_sync(0xffffffffu, d, o);

    const float SC = LOG2E_F / TAU_F;  // fold exp2-conversion + 1/TAU into A operand
    g_u[(size_t)row * DD + lane]      = un0 * SC;
    g_u[(size_t)row * DD + lane + 32] = un1 * SC;
    g_w[(size_t)row * DD + lane]      = un0 + vn0;
    g_w[(size_t)row * DD + lane + 32] = un1 + vn1;
    if (lane == 0) g_pos[row] = d * (1.0f / TAU_F);
}

// ---------------------------------------------------------------------------
// Kernel 2: fused GEMM + exp + row-sum.
// 128x128 tile per block, K=64 split in two 32-deep slabs (stay <48KB smem).
// 256 threads, each an 8x8 register micro-tile. Epilogue: ex2.approx + row
// sums reduced across the 16 threads sharing a row, written to g_partial.
// ---------------------------------------------------------------------------
__global__ void __launch_bounds__(256, 2) gemm_exp_kernel() {
    __shared__ __align__(16) float As[32][132];  // [k][m], pad to 132 (16B-aligned rows)
    __shared__ __align__(16) float Ws[32][132];  // [k][n]

    const int bm  = blockIdx.y;
    const int bn  = blockIdx.x;
    const int tid = threadIdx.x;
    const int tx  = tid & 15;   // column group
    const int ty  = tid >> 4;   // row group

    float acc[8][8];
#pragma unroll
    for (int i = 0; i < 8; i++)
#pragma unroll
        for (int j = 0; j < 8; j++) acc[i][j] = 0.f;

    const float4* Ug = (const float4*)(g_u + (size_t)bm * 128 * DD);
    const float4* Wg = (const float4*)(g_w + (size_t)bn * 128 * DD);

    for (int kt = 0; kt < 2; kt++) {
        // Load 128 rows x 32 k (8 float4 per row) of both tiles, transposed into smem.
#pragma unroll
        for (int it = 0; it < 4; it++) {
            int idx = tid + it * 256;      // 0..1023
            int row = idx >> 3;
            int k4  = idx & 7;
            float4 a = Ug[row * 16 + kt * 8 + k4];
            float4 b = Wg[row * 16 + kt * 8 + k4];
            int k = k4 * 4;
            As[k][row] = a.x; As[k + 1][row] = a.y; As[k + 2][row] = a.z; As[k + 3][row] = a.w;
            Ws[k][row] = b.x; Ws[k + 1][row] = b.y; Ws[k + 2][row] = b.z; Ws[k + 3][row] = b.w;
        }
        __syncthreads();

#pragma unroll 4
        for (int k = 0; k < 32; k++) {
            float4 a0 = *(const float4*)&As[k][ty * 8];
            float4 a1 = *(const float4*)&As[k][ty * 8 + 4];
            float4 b0 = *(const float4*)&Ws[k][tx * 8];
            float4 b1 = *(const float4*)&Ws[k][tx * 8 + 4];
            float av[8] = {a0.x, a0.y, a0.z, a0.w, a1.x, a1.y, a1.z, a1.w};
            float bv[8] = {b0.x, b0.y, b0.z, b0.w, b1.x, b1.y, b1.z, b1.w};
#pragma unroll
            for (int i = 0; i < 8; i++)
#pragma unroll
                for (int j = 0; j < 8; j++)
                    acc[i][j] = fmaf(av[i], bv[j], acc[i][j]);
        }
        __syncthreads();
    }

    // Epilogue: acc already = dot * log2e/TAU -> exp2, sum along j.
    float rs[8];
#pragma unroll
    for (int i = 0; i < 8; i++) {
        float s = 0.f;
#pragma unroll
        for (int j = 0; j < 8; j++) {
            float e;
            asm("ex2.approx.ftz.f32 %0, %1;" : "=f"(e) : "f"(acc[i][j]));
            s += e;
        }
        rs[i] = s;
    }

    // Cross-thread row reduction: 16 threads (tx) per row. Reuse Ws as scratch.
    float* red = &Ws[0][0];  // 16*132 floats used, fits in 32*132
#pragma unroll
    for (int i = 0; i < 8; i++) red[tx * 132 + ty * 8 + i] = rs[i];
    __syncthreads();

    if (tid < 128) {
        float s = 0.f;
#pragma unroll
        for (int x = 0; x < 16; x++) s += red[x * 132 + tid];
        g_partial[(size_t)bn * NN + bm * 128 + tid] = s;  // deterministic (no atomics)
    }
}

// ---------------------------------------------------------------------------
// Kernel 3: per-row total = sum of 128 column-block partials (fixed order),
// per-row loss, block-level sum.
// ---------------------------------------------------------------------------
__global__ void reduce_kernel() {
    int r = blockIdx.x * blockDim.x + threadIdx.x;  // 64 blocks * 256 = 16384
    float t = 0.f;
#pragma unroll 8
    for (int cb = 0; cb < NN / 128; cb++) t += g_partial[(size_t)cb * NN + r];
    float lr = logf(t + EPS_F) - g_pos[r];

    __shared__ float sm[256];
    sm[threadIdx.x] = lr;
    __syncthreads();
    for (int o = 128; o; o >>= 1) {
        if (threadIdx.x < o) sm[threadIdx.x] += sm[threadIdx.x + o];
        __syncthreads();
    }
    if (threadIdx.x == 0) g_blocksum[blockIdx.x] = sm[0];
}

// ---------------------------------------------------------------------------
// Kernel 4: final mean.
// ---------------------------------------------------------------------------
__global__ void final_kernel(float* __restrict__ out) {
    __shared__ float sm[64];
    int t = threadIdx.x;
    sm[t] = g_blocksum[t];
    __syncthreads();
    for (int o = 32; o; o >>= 1) {
        if (t < o) sm[t] += sm[t + o];
        __syncthreads();
    }
    if (t == 0) out[0] = sm[0] * (1.0f / (float)NN);
}

// ---------------------------------------------------------------------------
extern "C" void kernel_launch(void* const* d_in, const int* in_sizes, int n_in,
                              void* d_out, int out_size) {
    const float* U = (const float*)d_in[0];   // user_embed   [16384, 64] f32
    const float* I = (const float*)d_in[1];   // pos_item_embed [16384, 64] f32
    float* out = (float*)d_out;               // scalar f32

    prep_kernel<<<NN / 8, 256>>>(U, I);

    dim3 grid(NN / 128, NN / 128);            // 128 x 128 blocks
    gemm_exp_kernel<<<grid, 256>>>();

    reduce_kernel<<<NN / 256, 256>>>();
    final_kernel<<<1, 64>>>(out);
}

// round 3
// speedup vs baseline: 3.8222x; 3.8222x over previous
#include <cuda_runtime.h>
#include <cuda_bf16.h>
#include <cstdint>

#define NN 16384
#define DD 64
#define KK 192          // virtual K: [uh|uh|ul] . [wh|wl|wh]
#define KCH 96          // K per pipeline chunk (2 chunks)
#define SROW 104        // smem row stride in bf16 (208 B, 16B-aligned, conflict-free frags)

constexpr float TAU_F   = 0.28f;
constexpr float EPS_F   = 1e-8f;
constexpr float LOG2E_F = 1.4426950408889634f;

// Scratch (allocation-free: __device__ globals)
__device__ __nv_bfloat16 g_a[NN * KK];        // A rows: [uh | uh | ul], scaled by log2e/TAU
__device__ __nv_bfloat16 g_b[NN * KK];        // B rows: [wh | wl | wh], w = u_n + i_n
__device__ float g_pos[NN];
__device__ float g_partial[(NN / 128) * NN];  // per-column-block partial row sums
__device__ float g_blocksum[64];

__device__ __forceinline__ uint32_t smem_u32(const void* p) {
    uint32_t a;
    asm("{ .reg .u64 t; cvta.to.shared.u64 t, %1; cvt.u32.u64 %0, t; }" : "=r"(a) : "l"(p));
    return a;
}
__device__ __forceinline__ void cp16(uint32_t saddr, const void* g) {
    asm volatile("cp.async.ca.shared.global [%0], [%1], 16;" :: "r"(saddr), "l"(g));
}
__device__ __forceinline__ uint32_t lds32(uint32_t a) {
    uint32_t v;
    asm volatile("ld.shared.b32 %0, [%1];" : "=r"(v) : "r"(a));
    return v;
}
__device__ __forceinline__ void mma16816(float* c, const uint32_t* a, const uint32_t* b) {
    asm volatile(
        "mma.sync.aligned.m16n8k16.row.col.f32.bf16.bf16.f32 "
        "{%0,%1,%2,%3}, {%4,%5,%6,%7}, {%8,%9}, {%0,%1,%2,%3};"
        : "+f"(c[0]), "+f"(c[1]), "+f"(c[2]), "+f"(c[3])
        : "r"(a[0]), "r"(a[1]), "r"(a[2]), "r"(a[3]), "r"(b[0]), "r"(b[1]));
}

// ---------------------------------------------------------------------------
// Kernel 1: normalize, split into bf16 hi/lo, build A/B operand matrices.
// ---------------------------------------------------------------------------
__global__ void prep_kernel(const float* __restrict__ U, const float* __restrict__ I) {
    int row  = blockIdx.x * 8 + (threadIdx.x >> 5);
    int lane = threadIdx.x & 31;

    const float* up = U + (size_t)row * DD;
    const float* ip = I + (size_t)row * DD;
    float u0 = up[lane], u1 = up[lane + 32];
    float i0 = ip[lane], i1 = ip[lane + 32];

    float su = u0 * u0 + u1 * u1;
    float si = i0 * i0 + i1 * i1;
#pragma unroll
    for (int o = 16; o; o >>= 1) {
        su += __shfl_xor_sync(0xffffffffu, su, o);
        si += __shfl_xor_sync(0xffffffffu, si, o);
    }
    float inu = rsqrtf(fmaxf(su, 1e-24f));
    float ini = rsqrtf(fmaxf(si, 1e-24f));

    float un0 = u0 * inu, un1 = u1 * inu;
    float vn0 = i0 * ini, vn1 = i1 * ini;

    float d = un0 * vn0 + un1 * vn1;
#pragma unroll
    for (int o = 16; o; o >>= 1) d += __shfl_xor_sync(0xffffffffu, d, o);

    const float SC = LOG2E_F / TAU_F;   // GEMM result directly = log2 of each exp term
    float a0 = un0 * SC, a1 = un1 * SC;
    float w0 = un0 + vn0, w1 = un1 + vn1;

    __nv_bfloat16 ah0 = __float2bfloat16(a0);
    __nv_bfloat16 ah1 = __float2bfloat16(a1);
    __nv_bfloat16 al0 = __float2bfloat16(a0 - __bfloat162float(ah0));
    __nv_bfloat16 al1 = __float2bfloat16(a1 - __bfloat162float(ah1));
    __nv_bfloat16 wh0 = __float2bfloat16(w0);
    __nv_bfloat16 wh1 = __float2bfloat16(w1);
    __nv_bfloat16 wl0 = __float2bfloat16(w0 - __bfloat162float(wh0));
    __nv_bfloat16 wl1 = __float2bfloat16(w1 - __bfloat162float(wh1));

    size_t base = (size_t)row * KK;
    g_a[base +   0 + lane] = ah0;  g_a[base +  32 + lane] = ah1;
    g_a[base +  64 + lane] = ah0;  g_a[base +  96 + lane] = ah1;
    g_a[base + 128 + lane] = al0;  g_a[base + 160 + lane] = al1;
    g_b[base +   0 + lane] = wh0;  g_b[base +  32 + lane] = wh1;
    g_b[base +  64 + lane] = wl0;  g_b[base +  96 + lane] = wl1;
    g_b[base + 128 + lane] = wh0;  g_b[base + 160 + lane] = wh1;

    if (lane == 0) g_pos[row] = d * (1.0f / TAU_F);
}

// ---------------------------------------------------------------------------
// Kernel 2: bf16 mma.sync GEMM (128x128 tile, K=192 in two 96-chunks,
// cp.async double-buffered) + ex2 + row-sum epilogue, fully in registers.
// 8 warps in 2(M) x 4(N); warp tile 64x32 (4 m-frags x 4 n-frags m16n8k16).
// ---------------------------------------------------------------------------
__global__ void __launch_bounds__(256, 2) gemm_exp_kernel() {
    extern __shared__ __align__(16) char smem[];
    const int BUF = 128 * SROW * 2;         // 26624 B per matrix per stage
    uint32_t sb = smem_u32(smem);
    // stage s: A at sb + s*2*BUF, B at sb + s*2*BUF + BUF

    const int tid  = threadIdx.x;
    const int wid  = tid >> 5;
    const int lane = tid & 31;
    const int wm   = wid >> 2;              // 0..1  (M half)
    const int wn   = wid & 3;               // 0..3  (N quarter)
    const int g    = lane >> 2;             // 0..7
    const int t4   = lane & 3;              // 0..3
    const int bm = blockIdx.y, bn = blockIdx.x;

    const char* Ag = (const char*)g_a + (size_t)bm * 128 * (KK * 2);
    const char* Bg = (const char*)g_b + (size_t)bn * 128 * (KK * 2);

    // Issue cp.async for both chunks up-front (chunk ch covers k in [ch*96, ch*96+96))
#pragma unroll
    for (int ch = 0; ch < 2; ch++) {
        uint32_t sA = sb + ch * 2 * BUF;
        uint32_t sB = sA + BUF;
        const char* Agc = Ag + ch * (KCH * 2);
        const char* Bgc = Bg + ch * (KCH * 2);
#pragma unroll
        for (int it = 0; it < 6; it++) {
            int idx = it * 256 + tid;       // 0..1535 over (row, 12 x 16B)
            int row = idx / 12;
            int c   = idx - row * 12;
            uint32_t so = (uint32_t)(row * (SROW * 2) + c * 16);
            size_t   go = (size_t)row * (KK * 2) + c * 16;
            cp16(sA + so, Agc + go);
            cp16(sB + so, Bgc + go);
        }
        asm volatile("cp.async.commit_group;" ::: "memory");
    }

    float acc[4][4][4];
#pragma unroll
    for (int i = 0; i < 4; i++)
#pragma unroll
        for (int j = 0; j < 4; j++)
#pragma unroll
            for (int r = 0; r < 4; r++) acc[i][j][r] = 0.f;

#pragma unroll
    for (int ch = 0; ch < 2; ch++) {
        asm volatile("cp.async.wait_group %0;" :: "n"(1) : "memory");  // chunk ch ready
        __syncthreads();
        uint32_t sA = sb + ch * 2 * BUF;
        uint32_t sB = sA + BUF;

#pragma unroll
        for (int ks = 0; ks < KCH / 16; ks++) {     // 6 k-steps of 16
            const int kb = ks * 32 + t4 * 4;        // byte offset of (k0 + 2*t4) bf16
            uint32_t a[4][4], b[4][2];
#pragma unroll
            for (int mf = 0; mf < 4; mf++) {
                uint32_t base = sA + (uint32_t)((wm * 64 + mf * 16 + g) * (SROW * 2) + kb);
                a[mf][0] = lds32(base);
                a[mf][1] = lds32(base + 8 * (SROW * 2));
                a[mf][2] = lds32(base + 16);
                a[mf][3] = lds32(base + 8 * (SROW * 2) + 16);
            }
#pragma unroll
            for (int nf = 0; nf < 4; nf++) {
                uint32_t base = sB + (uint32_t)((wn * 32 + nf * 8 + g) * (SROW * 2) + kb);
                b[nf][0] = lds32(base);
                b[nf][1] = lds32(base + 16);
            }
#pragma unroll
            for (int mf = 0; mf < 4; mf++)
#pragma unroll
                for (int nf = 0; nf < 4; nf++)
                    mma16816(acc[mf][nf], a[mf], b[nf]);
        }
        if (ch == 0) __syncthreads();   // all reads of stage 0 done before... (buffers独立, sync for stage1 writes already landed via wait_group)
    }

    // ---------------- Epilogue: exp2 + row sums (deterministic) ----------------
    // Lane owns C rows (g, g+8) per m-frag; cols 2*t4, 2*t4+1 per n-frag.
    float rs0[4], rs1[4];
#pragma unroll
    for (int mf = 0; mf < 4; mf++) {
        float s0 = 0.f, s1 = 0.f;
#pragma unroll
        for (int nf = 0; nf < 4; nf++) {
            float e0, e1, e2, e3;
            asm("ex2.approx.ftz.f32 %0, %1;" : "=f"(e0) : "f"(acc[mf][nf][0]));
            asm("ex2.approx.ftz.f32 %0, %1;" : "=f"(e1) : "f"(acc[mf][nf][1]));
            asm("ex2.approx.ftz.f32 %0, %1;" : "=f"(e2) : "f"(acc[mf][nf][2]));
            asm("ex2.approx.ftz.f32 %0, %1;" : "=f"(e3) : "f"(acc[mf][nf][3]));
            s0 += e0 + e1;
            s1 += e2 + e3;
        }
        rs0[mf] = s0; rs1[mf] = s1;
    }
#pragma unroll
    for (int mf = 0; mf < 4; mf++) {
        rs0[mf] += __shfl_xor_sync(0xffffffffu, rs0[mf], 1);
        rs0[mf] += __shfl_xor_sync(0xffffffffu, rs0[mf], 2);
        rs1[mf] += __shfl_xor_sync(0xffffffffu, rs1[mf], 1);
        rs1[mf] += __shfl_xor_sync(0xffffffffu, rs1[mf], 2);
    }

    __syncthreads();                         // done with smem tiles; reuse as reduction scratch
    float* red = (float*)smem;               // [128 rows][4 wn]
    if (t4 == 0) {
#pragma unroll
        for (int mf = 0; mf < 4; mf++) {
            int r0 = wm * 64 + mf * 16 + g;
            red[r0 * 4 + wn]       = rs0[mf];
            red[(r0 + 8) * 4 + wn] = rs1[mf];
        }
    }
    __syncthreads();
    if (tid < 128) {
        float s = (red[tid * 4 + 0] + red[tid * 4 + 1]) +
                  (red[tid * 4 + 2] + red[tid * 4 + 3]);
        g_partial[(size_t)bn * NN + bm * 128 + tid] = s;   // fixed order, no atomics
    }
}

// ---------------------------------------------------------------------------
// Kernel 3: per-row total over 128 column-block partials, loss, block sums.
// ---------------------------------------------------------------------------
__global__ void reduce_kernel() {
    int r = blockIdx.x * blockDim.x + threadIdx.x;
    float t = 0.f;
#pragma unroll 8
    for (int cb = 0; cb < NN / 128; cb++) t += g_partial[(size_t)cb * NN + r];
    float lr = logf(t + EPS_F) - g_pos[r];

    __shared__ float sm[256];
    sm[threadIdx.x] = lr;
    __syncthreads();
    for (int o = 128; o; o >>= 1) {
        if (threadIdx.x < o) sm[threadIdx.x] += sm[threadIdx.x + o];
        __syncthreads();
    }
    if (threadIdx.x == 0) g_blocksum[blockIdx.x] = sm[0];
}

__global__ void final_kernel(float* __restrict__ out) {
    __shared__ float sm[64];
    int t = threadIdx.x;
    sm[t] = g_blocksum[t];
    __syncthreads();
    for (int o = 32; o; o >>= 1) {
        if (t < o) sm[t] += sm[t + o];
        __syncthreads();
    }
    if (t == 0) out[0] = sm[0] * (1.0f / (float)NN);
}

// ---------------------------------------------------------------------------
extern "C" void kernel_launch(void* const* d_in, const int* in_sizes, int n_in,
                              void* d_out, int out_size) {
    const float* U = (const float*)d_in[0];
    const float* I = (const float*)d_in[1];
    float* out = (float*)d_out;

    const int SMEM_BYTES = 4 * 128 * SROW * 2;   // 106496
    cudaFuncSetAttribute(gemm_exp_kernel,
                         cudaFuncAttributeMaxDynamicSharedMemorySize, SMEM_BYTES);

    prep_kernel<<<NN / 8, 256>>>(U, I);

    dim3 grid(NN / 128, NN / 128);
    gemm_exp_kernel<<<grid, 256, SMEM_BYTES>>>();

    reduce_kernel<<<NN / 256, 256>>>();
    final_kernel<<<1, 64>>>(out);
}

// round 5
// speedup vs baseline: 4.1621x; 1.0889x over previous
#include <cuda_runtime.h>
#include <cuda_bf16.h>
#include <cstdint>

#define NN 16384
#define DD 64
#define KK 192           // virtual K: [uh|uh|ul] . [wh|wl|wh]
#define SROWB 384        // smem row stride bytes = 24 x 16B chunks (full K row)

constexpr float TAU_F   = 0.28f;
constexpr float EPS_F   = 1e-8f;
constexpr float LOG2E_F = 1.4426950408889634f;

// Scratch (allocation-free: __device__ globals)
__device__ __nv_bfloat16 g_a[NN * KK];        // A rows: [uh | uh | ul], scaled by log2e/TAU
__device__ __nv_bfloat16 g_b[NN * KK];        // B rows: [wh | wl | wh], w = u_n + i_n
__device__ float g_pos[NN];
__device__ float g_partial[(NN / 128) * NN];  // per-column-block partial row sums
__device__ float g_blocksum[64];

__device__ __forceinline__ uint32_t smem_u32(const void* p) {
    uint32_t a;
    asm("{ .reg .u64 t; cvta.to.shared.u64 t, %1; cvt.u32.u64 %0, t; }" : "=r"(a) : "l"(p));
    return a;
}
__device__ __forceinline__ void cp16(uint32_t saddr, const void* g) {
    asm volatile("cp.async.cg.shared.global [%0], [%1], 16;" :: "r"(saddr), "l"(g));
}
__device__ __forceinline__ void ldsm_x4(uint32_t* r, uint32_t addr) {
    asm volatile("ldmatrix.sync.aligned.m8n8.x4.shared.b16 {%0,%1,%2,%3}, [%4];"
                 : "=r"(r[0]), "=r"(r[1]), "=r"(r[2]), "=r"(r[3]) : "r"(addr));
}
__device__ __forceinline__ void mma16816(float* c, const uint32_t* a,
                                         uint32_t b0, uint32_t b1) {
    asm volatile(
        "mma.sync.aligned.m16n8k16.row.col.f32.bf16.bf16.f32 "
        "{%0,%1,%2,%3}, {%4,%5,%6,%7}, {%8,%9}, {%0,%1,%2,%3};"
        : "+f"(c[0]), "+f"(c[1]), "+f"(c[2]), "+f"(c[3])
        : "r"(a[0]), "r"(a[1]), "r"(a[2]), "r"(a[3]), "r"(b0), "r"(b1));
}

// ---------------------------------------------------------------------------
// Kernel 1: normalize, split into bf16 hi/lo, build A/B operand matrices.
// ---------------------------------------------------------------------------
__global__ void prep_kernel(const float* __restrict__ U, const float* __restrict__ I) {
    int row  = blockIdx.x * 8 + (threadIdx.x >> 5);
    int lane = threadIdx.x & 31;

    const float* up = U + (size_t)row * DD;
    const float* ip = I + (size_t)row * DD;
    float u0 = up[lane], u1 = up[lane + 32];
    float i0 = ip[lane], i1 = ip[lane + 32];

    float su = u0 * u0 + u1 * u1;
    float si = i0 * i0 + i1 * i1;
#pragma unroll
    for (int o = 16; o; o >>= 1) {
        su += __shfl_xor_sync(0xffffffffu, su, o);
        si += __shfl_xor_sync(0xffffffffu, si, o);
    }
    float inu = rsqrtf(fmaxf(su, 1e-24f));
    float ini = rsqrtf(fmaxf(si, 1e-24f));

    float un0 = u0 * inu, un1 = u1 * inu;
    float vn0 = i0 * ini, vn1 = i1 * ini;

    float d = un0 * vn0 + un1 * vn1;
#pragma unroll
    for (int o = 16; o; o >>= 1) d += __shfl_xor_sync(0xffffffffu, d, o);

    const float SC = LOG2E_F / TAU_F;   // GEMM result directly = log2 of each exp term
    float a0 = un0 * SC, a1 = un1 * SC;
    float w0 = un0 + vn0, w1 = un1 + vn1;

    __nv_bfloat16 ah0 = __float2bfloat16(a0);
    __nv_bfloat16 ah1 = __float2bfloat16(a1);
    __nv_bfloat16 al0 = __float2bfloat16(a0 - __bfloat162float(ah0));
    __nv_bfloat16 al1 = __float2bfloat16(a1 - __bfloat162float(ah1));
    __nv_bfloat16 wh0 = __float2bfloat16(w0);
    __nv_bfloat16 wh1 = __float2bfloat16(w1);
    __nv_bfloat16 wl0 = __float2bfloat16(w0 - __bfloat162float(wh0));
    __nv_bfloat16 wl1 = __float2bfloat16(w1 - __bfloat162float(wh1));

    size_t base = (size_t)row * KK;
    g_a[base +   0 + lane] = ah0;  g_a[base +  32 + lane] = ah1;
    g_a[base +  64 + lane] = ah0;  g_a[base +  96 + lane] = ah1;
    g_a[base + 128 + lane] = al0;  g_a[base + 160 + lane] = al1;
    g_b[base +   0 + lane] = wh0;  g_b[base +  32 + lane] = wh1;
    g_b[base +  64 + lane] = wl0;  g_b[base +  96 + lane] = wl1;
    g_b[base + 128 + lane] = wh0;  g_b[base + 160 + lane] = wh1;

    if (lane == 0) g_pos[row] = d * (1.0f / TAU_F);
}

// ---------------------------------------------------------------------------
// Kernel 2: bf16 mma.sync GEMM, 128x128 tile, whole K=192 resident in smem,
// ldmatrix fragment loads, + ex2 + row-sum epilogue in registers.
// 8 warps 2(M) x 4(N); warp tile 64x32.
// Smem: rows are exactly 24 x 16B chunks (384B); chunk swizzle c ^ (row & 7)
// (XOR touches only the low 3 bits of the chunk index -> stays in-row).
// ---------------------------------------------------------------------------
__global__ void __launch_bounds__(256, 2) gemm_exp_kernel() {
    extern __shared__ __align__(16) char smem[];
    const uint32_t sb = smem_u32(smem);
    const uint32_t sA = sb;
    const uint32_t sB = sb + 128 * SROWB;     // 48 KB each

    const int tid  = threadIdx.x;
    const int wid  = tid >> 5;
    const int lane = tid & 31;
    const int wm   = wid >> 2;                // 0..1
    const int wn   = wid & 3;                 // 0..3
    const int bm = blockIdx.y, bn = blockIdx.x;

    const char* Ag = (const char*)g_a + (size_t)bm * 128 * (KK * 2);
    const char* Bg = (const char*)g_b + (size_t)bn * 128 * (KK * 2);

    // Load both full tiles: 128 rows x 24 chunks(16B) each operand.
#pragma unroll
    for (int it = 0; it < 12; it++) {
        int idx = it * 256 + tid;             // 0..3071
        int row = idx / 24;
        int c   = idx - row * 24;
        uint32_t so = (uint32_t)(row * SROWB + ((c ^ (row & 7)) << 4));
        size_t   go = (size_t)row * (KK * 2) + c * 16;
        cp16(sA + so, Ag + go);
        cp16(sB + so, Bg + go);
    }
    asm volatile("cp.async.commit_group;" ::: "memory");

    float acc[4][4][4];
#pragma unroll
    for (int i = 0; i < 4; i++)
#pragma unroll
        for (int j = 0; j < 4; j++)
#pragma unroll
            for (int r = 0; r < 4; r++) acc[i][j][r] = 0.f;

    asm volatile("cp.async.wait_group 0;" ::: "memory");
    __syncthreads();

    const int lr16 = lane & 15;               // ldmatrix row within 16
    const int lhi  = lane >> 4;               // k-chunk half select

#pragma unroll
    for (int ks = 0; ks < KK / 16; ks++) {    // 12 k-steps
        const int ch = 2 * ks + lhi;          // 16B chunk index (0..23)
        uint32_t a[4][4];
#pragma unroll
        for (int mf = 0; mf < 4; mf++) {
            int row = wm * 64 + mf * 16 + lr16;
            ldsm_x4(a[mf], sA + row * SROWB + ((ch ^ (row & 7)) << 4));
        }
        uint32_t bfr[2][4];
#pragma unroll
        for (int p = 0; p < 2; p++) {
            int row = wn * 32 + p * 16 + lr16;
            ldsm_x4(bfr[p], sB + row * SROWB + ((ch ^ (row & 7)) << 4));
        }
        // bfr[p] = {b0(nf=2p), b0(nf=2p+1), b1(nf=2p), b1(nf=2p+1)}
#pragma unroll
        for (int mf = 0; mf < 4; mf++) {
            mma16816(acc[mf][0], a[mf], bfr[0][0], bfr[0][2]);
            mma16816(acc[mf][1], a[mf], bfr[0][1], bfr[0][3]);
            mma16816(acc[mf][2], a[mf], bfr[1][0], bfr[1][2]);
            mma16816(acc[mf][3], a[mf], bfr[1][1], bfr[1][3]);
        }
    }

    // ---------------- Epilogue: exp2 + row sums (deterministic) ----------------
    const int g  = lane >> 2;                 // row-in-frag
    const int t4 = lane & 3;
    float rs0[4], rs1[4];
#pragma unroll
    for (int mf = 0; mf < 4; mf++) {
        float s0 = 0.f, s1 = 0.f;
#pragma unroll
        for (int nf = 0; nf < 4; nf++) {
            float e0, e1, e2, e3;
            asm("ex2.approx.ftz.f32 %0, %1;" : "=f"(e0) : "f"(acc[mf][nf][0]));
            asm("ex2.approx.ftz.f32 %0, %1;" : "=f"(e1) : "f"(acc[mf][nf][1]));
            asm("ex2.approx.ftz.f32 %0, %1;" : "=f"(e2) : "f"(acc[mf][nf][2]));
            asm("ex2.approx.ftz.f32 %0, %1;" : "=f"(e3) : "f"(acc[mf][nf][3]));
            s0 += e0 + e1;
            s1 += e2 + e3;
        }
        rs0[mf] = s0; rs1[mf] = s1;
    }
#pragma unroll
    for (int mf = 0; mf < 4; mf++) {
        rs0[mf] += __shfl_xor_sync(0xffffffffu, rs0[mf], 1);
        rs0[mf] += __shfl_xor_sync(0xffffffffu, rs0[mf], 2);
        rs1[mf] += __shfl_xor_sync(0xffffffffu, rs1[mf], 1);
        rs1[mf] += __shfl_xor_sync(0xffffffffu, rs1[mf], 2);
    }

    __syncthreads();                          // tiles no longer needed; reuse smem
    float* red = (float*)smem;                // [128 rows][4 wn]
    if (t4 == 0) {
#pragma unroll
        for (int mf = 0; mf < 4; mf++) {
            int r0 = wm * 64 + mf * 16 + g;
            red[r0 * 4 + wn]       = rs0[mf];
            red[(r0 + 8) * 4 + wn] = rs1[mf];
        }
    }
    __syncthreads();
    if (tid < 128) {
        float s = (red[tid * 4 + 0] + red[tid * 4 + 1]) +
                  (red[tid * 4 + 2] + red[tid * 4 + 3]);
        g_partial[(size_t)bn * NN + bm * 128 + tid] = s;   // fixed order, no atomics
    }
}

// ---------------------------------------------------------------------------
// Kernel 3: per-row total over 128 column-block partials, loss, block sums.
// ---------------------------------------------------------------------------
__global__ void reduce_kernel() {
    int r = blockIdx.x * blockDim.x + threadIdx.x;
    float t = 0.f;
#pragma unroll 8
    for (int cb = 0; cb < NN / 128; cb++) t += g_partial[(size_t)cb * NN + r];
    float lr = logf(t + EPS_F) - g_pos[r];

    __shared__ float sm[256];
    sm[threadIdx.x] = lr;
    __syncthreads();
    for (int o = 128; o; o >>= 1) {
        if (threadIdx.x < o) sm[threadIdx.x] += sm[threadIdx.x + o];
        __syncthreads();
    }
    if (threadIdx.x == 0) g_blocksum[blockIdx.x] = sm[0];
}

__global__ void final_kernel(float* __restrict__ out) {
    __shared__ float sm[64];
    int t = threadIdx.x;
    sm[t] = g_blocksum[t];
    __syncthreads();
    for (int o = 32; o; o >>= 1) {
        if (t < o) sm[t] += sm[t + o];
        __syncthreads();
    }
    if (t == 0) out[0] = sm[0] * (1.0f / (float)NN);
}

// ---------------------------------------------------------------------------
extern "C" void kernel_launch(void* const* d_in, const int* in_sizes, int n_in,
                              void* d_out, int out_size) {
    const float* U = (const float*)d_in[0];
    const float* I = (const float*)d_in[1];
    float* out = (float*)d_out;

    const int SMEM_BYTES = 2 * 128 * SROWB;   // 98304
    cudaFuncSetAttribute(gemm_exp_kernel,
                         cudaFuncAttributeMaxDynamicSharedMemorySize, SMEM_BYTES);

    prep_kernel<<<NN / 8, 256>>>(U, I);

    dim3 grid(NN / 128, NN / 128);
    gemm_exp_kernel<<<grid, 256, SMEM_BYTES>>>();

    reduce_kernel<<<NN / 256, 256>>>();
    final_kernel<<<1, 64>>>(out);
}

// round 6
// speedup vs baseline: 6.3921x; 1.5358x over previous
#include <cuda_runtime.h>
#include <cuda_fp16.h>
#include <cstdint>

#define NN 16384
#define DD 64
#define KK 128           // virtual K: [uh|ul] . [wh|wh]  (fp16 split, drops only a*wl)
#define SROWB 256        // smem row stride bytes = 16 x 16B chunks (full K row)

constexpr float TAU_F   = 0.28f;
constexpr float EPS_F   = 1e-8f;
constexpr float LOG2E_F = 1.4426950408889634f;

// Scratch (allocation-free: __device__ globals)
__device__ __half g_a[NN * KK];               // A rows: [uh | ul], scaled by log2e/TAU
__device__ __half g_b[NN * KK];               // B rows: [wh | wh], w = u_n + i_n
__device__ float g_pos[NN];
__device__ float g_partial[(NN / 128) * NN];  // per-column-block partial row sums
__device__ float g_blocksum[64];

__device__ __forceinline__ uint32_t smem_u32(const void* p) {
    uint32_t a;
    asm("{ .reg .u64 t; cvta.to.shared.u64 t, %1; cvt.u32.u64 %0, t; }" : "=r"(a) : "l"(p));
    return a;
}
__device__ __forceinline__ void cp16(uint32_t saddr, const void* g) {
    asm volatile("cp.async.cg.shared.global [%0], [%1], 16;" :: "r"(saddr), "l"(g));
}
__device__ __forceinline__ void ldsm_x4(uint32_t* r, uint32_t addr) {
    asm volatile("ldmatrix.sync.aligned.m8n8.x4.shared.b16 {%0,%1,%2,%3}, [%4];"
                 : "=r"(r[0]), "=r"(r[1]), "=r"(r[2]), "=r"(r[3]) : "r"(addr));
}
__device__ __forceinline__ void mma16816(float* c, const uint32_t* a,
                                         uint32_t b0, uint32_t b1) {
    asm volatile(
        "mma.sync.aligned.m16n8k16.row.col.f32.f16.f16.f32 "
        "{%0,%1,%2,%3}, {%4,%5,%6,%7}, {%8,%9}, {%0,%1,%2,%3};"
        : "+f"(c[0]), "+f"(c[1]), "+f"(c[2]), "+f"(c[3])
        : "r"(a[0]), "r"(a[1]), "r"(a[2]), "r"(a[3]), "r"(b0), "r"(b1));
}

// ---------------------------------------------------------------------------
// Kernel 1: normalize, fp16 hi/lo split, build A/B operand matrices.
// ---------------------------------------------------------------------------
__global__ void prep_kernel(const float* __restrict__ U, const float* __restrict__ I) {
    int row  = blockIdx.x * 8 + (threadIdx.x >> 5);
    int lane = threadIdx.x & 31;

    const float* up = U + (size_t)row * DD;
    const float* ip = I + (size_t)row * DD;
    float u0 = up[lane], u1 = up[lane + 32];
    float i0 = ip[lane], i1 = ip[lane + 32];

    float su = u0 * u0 + u1 * u1;
    float si = i0 * i0 + i1 * i1;
#pragma unroll
    for (int o = 16; o; o >>= 1) {
        su += __shfl_xor_sync(0xffffffffu, su, o);
        si += __shfl_xor_sync(0xffffffffu, si, o);
    }
    float inu = rsqrtf(fmaxf(su, 1e-24f));
    float ini = rsqrtf(fmaxf(si, 1e-24f));

    float un0 = u0 * inu, un1 = u1 * inu;
    float vn0 = i0 * ini, vn1 = i1 * ini;

    float d = un0 * vn0 + un1 * vn1;
#pragma unroll
    for (int o = 16; o; o >>= 1) d += __shfl_xor_sync(0xffffffffu, d, o);

    const float SC = LOG2E_F / TAU_F;   // GEMM output directly = log2 of each exp term
    float a0 = un0 * SC, a1 = un1 * SC;
    float w0 = un0 + vn0, w1 = un1 + vn1;

    __half ah0 = __float2half_rn(a0);
    __half ah1 = __float2half_rn(a1);
    __half al0 = __float2half_rn(a0 - __half2float(ah0));
    __half al1 = __float2half_rn(a1 - __half2float(ah1));
    __half wh0 = __float2half_rn(w0);
    __half wh1 = __float2half_rn(w1);

    size_t base = (size_t)row * KK;
    // A = [ah | al]
    g_a[base +  0 + lane] = ah0;  g_a[base + 32 + lane] = ah1;
    g_a[base + 64 + lane] = al0;  g_a[base + 96 + lane] = al1;
    // B = [wh | wh]
    g_b[base +  0 + lane] = wh0;  g_b[base + 32 + lane] = wh1;
    g_b[base + 64 + lane] = wh0;  g_b[base + 96 + lane] = wh1;

    if (lane == 0) g_pos[row] = d * (1.0f / TAU_F);
}

// ---------------------------------------------------------------------------
// Kernel 2: fp16 mma.sync GEMM, 128x128 tile, whole K=128 resident in smem,
// ldmatrix fragment loads + ex2 + row-sum epilogue in registers.
// 8 warps 2(M) x 4(N); warp tile 64x32.
// Smem: rows = 16 x 16B chunks (256B); chunk swizzle c ^ (row & 7).
// ---------------------------------------------------------------------------
__global__ void __launch_bounds__(256, 2) gemm_exp_kernel() {
    extern __shared__ __align__(16) char smem[];
    const uint32_t sb = smem_u32(smem);
    const uint32_t sA = sb;
    const uint32_t sB = sb + 128 * SROWB;     // 32 KB each

    const int tid  = threadIdx.x;
    const int wid  = tid >> 5;
    const int lane = tid & 31;
    const int wm   = wid >> 2;                // 0..1
    const int wn   = wid & 3;                 // 0..3
    const int bm = blockIdx.y, bn = blockIdx.x;

    const char* Ag = (const char*)g_a + (size_t)bm * 128 * (KK * 2);
    const char* Bg = (const char*)g_b + (size_t)bn * 128 * (KK * 2);

    // Load both full tiles: 128 rows x 16 chunks(16B) each operand.
#pragma unroll
    for (int it = 0; it < 8; it++) {
        int idx = it * 256 + tid;             // 0..2047
        int row = idx >> 4;
        int c   = idx & 15;
        uint32_t so = (uint32_t)(row * SROWB + ((c ^ (row & 7)) << 4));
        size_t   go = (size_t)row * (KK * 2) + c * 16;
        cp16(sA + so, Ag + go);
        cp16(sB + so, Bg + go);
    }
    asm volatile("cp.async.commit_group;" ::: "memory");

    float acc[4][4][4];
#pragma unroll
    for (int i = 0; i < 4; i++)
#pragma unroll
        for (int j = 0; j < 4; j++)
#pragma unroll
            for (int r = 0; r < 4; r++) acc[i][j][r] = 0.f;

    asm volatile("cp.async.wait_group 0;" ::: "memory");
    __syncthreads();

    const int lr16 = lane & 15;               // ldmatrix row within 16
    const int lhi  = lane >> 4;               // k-chunk half select

#pragma unroll
    for (int ks = 0; ks < KK / 16; ks++) {    // 8 k-steps
        const int ch = 2 * ks + lhi;          // 16B chunk index (0..15)
        uint32_t a[4][4];
#pragma unroll
        for (int mf = 0; mf < 4; mf++) {
            int row = wm * 64 + mf * 16 + lr16;
            ldsm_x4(a[mf], sA + row * SROWB + ((ch ^ (row & 7)) << 4));
        }
        uint32_t bfr[2][4];
#pragma unroll
        for (int p = 0; p < 2; p++) {
            int row = wn * 32 + p * 16 + lr16;
            ldsm_x4(bfr[p], sB + row * SROWB + ((ch ^ (row & 7)) << 4));
        }
        // bfr[p] = {b0(nf=2p), b0(nf=2p+1), b1(nf=2p), b1(nf=2p+1)}
#pragma unroll
        for (int mf = 0; mf < 4; mf++) {
            mma16816(acc[mf][0], a[mf], bfr[0][0], bfr[0][2]);
            mma16816(acc[mf][1], a[mf], bfr[0][1], bfr[0][3]);
            mma16816(acc[mf][2], a[mf], bfr[1][0], bfr[1][2]);
            mma16816(acc[mf][3], a[mf], bfr[1][1], bfr[1][3]);
        }
    }

    // ---------------- Epilogue: exp2 + row sums (deterministic) ----------------
    const int g  = lane >> 2;                 // row-in-frag
    const int t4 = lane & 3;
    float rs0[4], rs1[4];
#pragma unroll
    for (int mf = 0; mf < 4; mf++) {
        float s0 = 0.f, s1 = 0.f;
#pragma unroll
        for (int nf = 0; nf < 4; nf++) {
            float e0, e1, e2, e3;
            asm("ex2.approx.ftz.f32 %0, %1;" : "=f"(e0) : "f"(acc[mf][nf][0]));
            asm("ex2.approx.ftz.f32 %0, %1;" : "=f"(e1) : "f"(acc[mf][nf][1]));
            asm("ex2.approx.ftz.f32 %0, %1;" : "=f"(e2) : "f"(acc[mf][nf][2]));
            asm("ex2.approx.ftz.f32 %0, %1;" : "=f"(e3) : "f"(acc[mf][nf][3]));
            s0 += e0 + e1;
            s1 += e2 + e3;
        }
        rs0[mf] = s0; rs1[mf] = s1;
    }
#pragma unroll
    for (int mf = 0; mf < 4; mf++) {
        rs0[mf] += __shfl_xor_sync(0xffffffffu, rs0[mf], 1);
        rs0[mf] += __shfl_xor_sync(0xffffffffu, rs0[mf], 2);
        rs1[mf] += __shfl_xor_sync(0xffffffffu, rs1[mf], 1);
        rs1[mf] += __shfl_xor_sync(0xffffffffu, rs1[mf], 2);
    }

    __syncthreads();                          // tiles no longer needed; reuse smem
    float* red = (float*)smem;                // [128 rows][4 wn]
    if (t4 == 0) {
#pragma unroll
        for (int mf = 0; mf < 4; mf++) {
            int r0 = wm * 64 + mf * 16 + g;
            red[r0 * 4 + wn]       = rs0[mf];
            red[(r0 + 8) * 4 + wn] = rs1[mf];
        }
    }
    __syncthreads();
    if (tid < 128) {
        float s = (red[tid * 4 + 0] + red[tid * 4 + 1]) +
                  (red[tid * 4 + 2] + red[tid * 4 + 3]);
        g_partial[(size_t)bn * NN + bm * 128 + tid] = s;   // fixed order, no atomics
    }
}

// ---------------------------------------------------------------------------
// Kernel 3: per-row total over 128 column-block partials, loss, block sums.
// ---------------------------------------------------------------------------
__global__ void reduce_kernel() {
    int r = blockIdx.x * blockDim.x + threadIdx.x;
    float t = 0.f;
#pragma unroll 8
    for (int cb = 0; cb < NN / 128; cb++) t += g_partial[(size_t)cb * NN + r];
    float lr = logf(t + EPS_F) - g_pos[r];

    __shared__ float sm[256];
    sm[threadIdx.x] = lr;
    __syncthreads();
    for (int o = 128; o; o >>= 1) {
        if (threadIdx.x < o) sm[threadIdx.x] += sm[threadIdx.x + o];
        __syncthreads();
    }
    if (threadIdx.x == 0) g_blocksum[blockIdx.x] = sm[0];
}

__global__ void final_kernel(float* __restrict__ out) {
    __shared__ float sm[64];
    int t = threadIdx.x;
    sm[t] = g_blocksum[t];
    __syncthreads();
    for (int o = 32; o; o >>= 1) {
        if (t < o) sm[t] += sm[t + o];
        __syncthreads();
    }
    if (t == 0) out[0] = sm[0] * (1.0f / (float)NN);
}

// ---------------------------------------------------------------------------
extern "C" void kernel_launch(void* const* d_in, const int* in_sizes, int n_in,
                              void* d_out, int out_size) {
    const float* U = (const float*)d_in[0];
    const float* I = (const float*)d_in[1];
    float* out = (float*)d_out;

    const int SMEM_BYTES = 2 * 128 * SROWB;   // 65536
    cudaFuncSetAttribute(gemm_exp_kernel,
                         cudaFuncAttributeMaxDynamicSharedMemorySize, SMEM_BYTES);

    prep_kernel<<<NN / 8, 256>>>(U, I);

    dim3 grid(NN / 128, NN / 128);
    gemm_exp_kernel<<<grid, 256, SMEM_BYTES>>>();

    reduce_kernel<<<NN / 256, 256>>>();
    final_kernel<<<1, 64>>>(out);
}